// round 1
// baseline (speedup 1.0000x reference)
#include <cuda_runtime.h>

#define BB 64
#define TT 512
#define HH 128
#define LL 8
#define OUTD 65
#define GG 512               // 4*H
#define CTAS_PER_LAYER 16
#define NCTA (LL * CTAS_PER_LAYER)   // 128
#define NTHR 128
#define NSTEPS (TT + LL - 1)          // 519

// outputs [B][T][OUT] then hT [L][B][H] then cT [L][B][H]
#define OUTBASE ((long long)BB * TT * OUTD)          // 2129920
#define STATESZ ((long long)LL * BB * HH)            // 65536
#define TOTALOUT (OUTBASE + 2 * STATESZ)             // 2260992

// ---------------- device scratch (static globals: no allocation) ----------
__device__ float g_hbuf[2][LL][HH][BB];   // double-buffered h, k-major [layer][k][b]
__device__ float g_xe[TT][HH][BB];        // embedded input, k-major
__device__ float g_h7[TT][HH][BB];        // layer-7 h for all t (for projection)
__device__ unsigned long long g_ctr = 0;  // monotonic arrival counter (replay-safe)
__device__ unsigned long long g_rel = 0;  // monotonic release phase

// ---------------- helpers ------------------------------------------------
__device__ __forceinline__ float sigf(float x) {
    return 1.0f / (1.0f + __expf(-x));
}
__device__ __forceinline__ float tanhf_(float x) {
    // 2*sigmoid(2x)-1; abs err ~1e-7, fine vs 1e-3 tolerance
    return 2.0f / (1.0f + __expf(-2.0f * x)) - 1.0f;
}

__device__ __forceinline__ void grid_barrier() {
    __syncthreads();
    if (threadIdx.x == 0) {
        __threadfence();
        unsigned long long my = atomicAdd(&g_ctr, 1ULL);
        unsigned long long phase = my / NCTA;
        if ((my % NCTA) == (NCTA - 1)) {
            __threadfence();
            *((volatile unsigned long long*)&g_rel) = phase + 1;
        } else {
            while (*((volatile unsigned long long*)&g_rel) <= phase) { }
        }
        __threadfence();
    }
    __syncthreads();
}

// ---------------- phase A: embedding gather, k-major ----------------------
__global__ void embed_kernel(const int* __restrict__ x,
                             const float* __restrict__ embed) {
    int t = blockIdx.x;
    int tid = threadIdx.x;          // 128 threads
    __shared__ int xv[BB];
    if (tid < BB) xv[tid] = x[tid * TT + t];
    __syncthreads();
    int b = tid >> 1, half = tid & 1;
    const float4* src = (const float4*)(embed + (long long)xv[b] * HH + half * 64);
#pragma unroll
    for (int i = 0; i < 16; i++) {
        float4 v = src[i];
        int k = half * 64 + i * 4;
        g_xe[t][k + 0][b] = v.x;
        g_xe[t][k + 1][b] = v.y;
        g_xe[t][k + 2][b] = v.z;
        g_xe[t][k + 3][b] = v.w;
    }
}

// ---------------- phase B: persistent wavefront LSTM ----------------------
extern __shared__ float smem[];
// smem layout: w_s[256*32] (32KB) | a_s[256*64] (64KB) | bias_s[32]
// gates reuse a_s region after the GEMM.

__global__ void __launch_bounds__(NTHR, 1)
lstm_kernel(const float* __restrict__ w_ih, const float* __restrict__ b_ih,
            const float* __restrict__ w_hh, const float* __restrict__ b_hh,
            float* __restrict__ d_out, long long out_size) {
    float* w_s    = smem;                  // 8192 floats
    float* a_s    = smem + 8192;           // 16384 floats
    float* bias_s = smem + 8192 + 16384;   // 32 floats
    float* g_sm   = a_s;                   // alias: gates [32][64]

    int layer = blockIdx.x / CTAS_PER_LAYER;
    int sub   = blockIdx.x % CTAS_PER_LAYER;
    int hc0   = sub * 8;                   // this CTA's 8 h-columns
    int tid   = threadIdx.x;

    // --- one-time: load weight slice into smem, combine biases ---
    for (int idx = tid; idx < 128 * 32; idx += NTHR) {
        int k = idx >> 5, c = idx & 31;
        int col = (c >> 3) * HH + hc0 + (c & 7);     // gate*128 + hcol
        w_s[k * 32 + c]         = w_ih[((long long)layer * HH + k) * GG + col];
        w_s[(k + 128) * 32 + c] = w_hh[((long long)layer * HH + k) * GG + col];
    }
    if (tid < 32) {
        int col = (tid >> 3) * HH + hc0 + (tid & 7);
        bias_s[tid] = b_ih[layer * GG + col] + b_hh[layer * GG + col];
    }
    // zero this CTA's h slices in both phase buffers (replay-safe init)
    for (int idx = tid; idx < 8 * BB; idx += NTHR) {
        int j = idx >> 6, b = idx & 63;
        g_hbuf[0][layer][hc0 + j][b] = 0.0f;
        g_hbuf[1][layer][hc0 + j][b] = 0.0f;
    }
    __threadfence();

    int tb = tid & 15;      // b-tile index: b0 = 4*tb
    int tc = tid >> 4;      // c-tile index: c0 = 4*tc  (tc in 0..7)
    float c_reg[4];         // persistent cell state for this thread's (j,b) cells
    c_reg[0] = c_reg[1] = c_reg[2] = c_reg[3] = 0.0f;

    const float4* wS = (const float4*)w_s;
    const float4* aS = (const float4*)a_s;

    for (int s = 0; s < NSTEPS; s++) {
        grid_barrier();
        int t = s - layer;
        if (t >= 0 && t < TT) {
            int prev = (s + 1) & 1;
            // ---- load A = [inp ; h] into smem (k-major, float4 copies) ----
            const float4* i4 = (layer == 0)
                ? (const float4*)&g_xe[t][0][0]
                : (const float4*)&g_hbuf[prev][layer - 1][0][0];
            const float4* h4 = (const float4*)&g_hbuf[prev][layer][0][0];
            float4* a4 = (float4*)a_s;
            for (int i = tid; i < 2048; i += NTHR) a4[i] = i4[i];
            for (int i = tid; i < 2048; i += NTHR) a4[2048 + i] = h4[i];
            __syncthreads();

            // ---- GEMM: C[4b x 4c] over K=256 ----
            float acc[4][4];
#pragma unroll
            for (int i = 0; i < 4; i++)
#pragma unroll
                for (int j = 0; j < 4; j++)
                    acc[i][j] = bias_s[4 * tc + j];

#pragma unroll 8
            for (int k = 0; k < 256; k++) {
                float4 av = aS[k * 16 + tb];
                float4 wv = wS[k * 8 + tc];
                acc[0][0] += av.x * wv.x; acc[0][1] += av.x * wv.y;
                acc[0][2] += av.x * wv.z; acc[0][3] += av.x * wv.w;
                acc[1][0] += av.y * wv.x; acc[1][1] += av.y * wv.y;
                acc[1][2] += av.y * wv.z; acc[1][3] += av.y * wv.w;
                acc[2][0] += av.z * wv.x; acc[2][1] += av.z * wv.y;
                acc[2][2] += av.z * wv.z; acc[2][3] += av.z * wv.w;
                acc[3][0] += av.w * wv.x; acc[3][1] += av.w * wv.y;
                acc[3][2] += av.w * wv.z; acc[3][3] += av.w * wv.w;
            }
            __syncthreads();   // done reading a_s; safe to overwrite with gates

            // ---- gate exchange via smem: g_sm[c][b] ----
#pragma unroll
            for (int j = 0; j < 4; j++)
#pragma unroll
                for (int i = 0; i < 4; i++)
                    g_sm[(4 * tc + j) * 64 + (4 * tb + i)] = acc[i][j];
            __syncthreads();

            // ---- fused elementwise: i,f,g,o -> c,h ----
            int b = tid & 63;
#pragma unroll
            for (int ii = 0; ii < 4; ii++) {
                int j = (tid >> 6) + 2 * ii;           // local h-col 0..7
                float gi = g_sm[(0 + j) * 64 + b];
                float gf = g_sm[(8 + j) * 64 + b];
                float gg = g_sm[(16 + j) * 64 + b];
                float go = g_sm[(24 + j) * 64 + b];
                float iv = sigf(gi);
                float fv = sigf(gf);
                float gv = tanhf_(gg);
                float ov = sigf(go);
                float cp = (t == 0) ? 0.0f : c_reg[ii];
                float cn = fv * cp + iv * gv;
                float hv = ov * tanhf_(cn);
                c_reg[ii] = cn;
                g_hbuf[s & 1][layer][hc0 + j][b] = hv;
                if (layer == LL - 1) g_h7[t][hc0 + j][b] = hv;
                if (t == TT - 1 && out_size >= TOTALOUT) {
                    long long base = OUTBASE + ((long long)layer * BB + b) * HH + hc0 + j;
                    d_out[base] = hv;
                    d_out[base + STATESZ] = cn;
                }
            }
            __threadfence();   // publish h before next barrier
        }
    }
}

// ---------------- phase C: output projection ------------------------------
__global__ void proj_kernel(const float* __restrict__ w_out,
                            const float* __restrict__ b_out,
                            float* __restrict__ d_out) {
    int t = blockIdx.x;
    __shared__ float h_s[HH * BB];   // 32 KB
    int tid = threadIdx.x;           // 128
    const float4* src = (const float4*)&g_h7[t][0][0];
    float4* dst4 = (float4*)h_s;
    for (int i = tid; i < 2048; i += 128) dst4[i] = src[i];
    __syncthreads();
    for (int idx = tid; idx < BB * OUTD; idx += 128) {
        int b = idx / OUTD, o = idx % OUTD;
        float acc = b_out[o];
#pragma unroll 8
        for (int k = 0; k < HH; k++)
            acc += h_s[k * 64 + b] * w_out[k * OUTD + o];
        d_out[((long long)b * TT + t) * OUTD + o] = acc;
    }
}

// ---------------- launch ---------------------------------------------------
extern "C" void kernel_launch(void* const* d_in, const int* in_sizes, int n_in,
                              void* d_out, int out_size) {
    const int*   x     = (const int*)d_in[0];
    const float* embed = (const float*)d_in[1];
    const float* w_ih  = (const float*)d_in[2];
    const float* b_ih  = (const float*)d_in[3];
    const float* w_hh  = (const float*)d_in[4];
    const float* b_hh  = (const float*)d_in[5];
    const float* w_out = (const float*)d_in[6];
    const float* b_out = (const float*)d_in[7];
    float* out = (float*)d_out;

    size_t smem_bytes = (8192 + 16384 + 32) * sizeof(float);   // ~96.1 KB
    cudaFuncSetAttribute(lstm_kernel, cudaFuncAttributeMaxDynamicSharedMemorySize,
                         (int)smem_bytes);

    embed_kernel<<<TT, 128>>>(x, embed);
    lstm_kernel<<<NCTA, NTHR, smem_bytes>>>(w_ih, b_ih, w_hh, b_hh, out,
                                            (long long)out_size);
    proj_kernel<<<TT, 128>>>(w_out, b_out, out);
}

// round 4
// speedup vs baseline: 1.0127x; 1.0127x over previous
#include <cuda_runtime.h>

#define BB 64
#define TT 512
#define HH 128
#define LL 8
#define OUTD 65
#define GG 512               // 4*H
#define CTAS_PER_LAYER 16
#define NCTA (LL * CTAS_PER_LAYER)   // 128
#define NTHR 128

// outputs [B][T][OUT] then hT [L][B][H] then cT [L][B][H]
#define OUTBASE ((long long)BB * TT * OUTD)
#define STATESZ ((long long)LL * BB * HH)
#define TOTALOUT (OUTBASE + 2 * STATESZ)

typedef unsigned long long u64;

// ---------------- device scratch (static globals: no allocation) ----------
__device__ float g_hbuf[2][LL][HH][BB];   // double-buffered h, k-major
__device__ float g_xe[TT][HH][BB];        // embedded input, k-major
__device__ float g_h7[TT][HH][BB];        // layer-7 h stream
// per-layer completion counters, padded to separate cache lines
__device__ unsigned int g_done[LL * 32];

// ---------------- helpers ------------------------------------------------
__device__ __forceinline__ float sigf(float x) {
    return 1.0f / (1.0f + __expf(-x));
}
__device__ __forceinline__ float tanhf_(float x) {
    return 2.0f / (1.0f + __expf(-2.0f * x)) - 1.0f;
}
__device__ __forceinline__ u64 pack2(float x, float y) {
    u64 r; asm("mov.b64 %0, {%1,%2};" : "=l"(r) : "f"(x), "f"(y)); return r;
}
#define FMA2(d, a, b) \
    asm("fma.rn.f32x2 %0, %1, %2, %0;" : "+l"(d) : "l"(a), "l"(b))

// ---------------- init: zero state + counters (replay-safe) ---------------
__global__ void init_kernel() {
    long long n = 2LL * LL * HH * BB;           // floats in g_hbuf
    float* p = &g_hbuf[0][0][0][0];
    long long i = (long long)blockIdx.x * blockDim.x + threadIdx.x;
    long long stride = (long long)gridDim.x * blockDim.x;
    for (; i < n; i += stride) p[i] = 0.0f;
    if (blockIdx.x == 0 && threadIdx.x < LL * 32)
        g_done[threadIdx.x] = 0u;
}

// ---------------- phase A: embedding gather, k-major ----------------------
__global__ void embed_kernel(const int* __restrict__ x,
                             const float* __restrict__ embed) {
    int t = blockIdx.x;
    int tid = threadIdx.x;
    __shared__ int xv[BB];
    if (tid < BB) xv[tid] = x[tid * TT + t];
    __syncthreads();
    int b = tid >> 1, half = tid & 1;
    const float4* src = (const float4*)(embed + (long long)xv[b] * HH + half * 64);
#pragma unroll
    for (int i = 0; i < 16; i++) {
        float4 v = src[i];
        int k = half * 64 + i * 4;
        g_xe[t][k + 0][b] = v.x;
        g_xe[t][k + 1][b] = v.y;
        g_xe[t][k + 2][b] = v.z;
        g_xe[t][k + 3][b] = v.w;
    }
}

// ---------------- phase B: persistent LSTM, per-layer flow control --------
extern __shared__ float smem[];
// layout: w2_s (u64[256*32], 64KB) | a_s (float[256*64], 64KB) | bias_s[32]

__global__ void __launch_bounds__(NTHR, 1)
lstm_kernel(const float* __restrict__ w_ih, const float* __restrict__ b_ih,
            const float* __restrict__ w_hh, const float* __restrict__ b_hh,
            float* __restrict__ d_out, long long out_size) {
    u64*   w2_s   = (u64*)smem;                      // 8192 u64
    float* a_s    = smem + 16384;                    // 16384 floats
    float* bias_s = smem + 16384 + 16384;            // 32 floats
    float* g_sm   = a_s;                             // gates alias [32][64]

    int layer = blockIdx.x / CTAS_PER_LAYER;
    int sub   = blockIdx.x % CTAS_PER_LAYER;
    int hc0   = sub * 8;
    int tid   = threadIdx.x;

    // one-time: weight slice -> smem, duplicated into f32x2 lanes
    for (int idx = tid; idx < 128 * 32; idx += NTHR) {
        int k = idx >> 5, c = idx & 31;
        int col = (c >> 3) * HH + hc0 + (c & 7);
        float wi = w_ih[((long long)layer * HH + k) * GG + col];
        float wh = w_hh[((long long)layer * HH + k) * GG + col];
        w2_s[k * 32 + c]         = pack2(wi, wi);
        w2_s[(k + 128) * 32 + c] = pack2(wh, wh);
    }
    if (tid < 32) {
        int col = (tid >> 3) * HH + hc0 + (tid & 7);
        bias_s[tid] = b_ih[layer * GG + col] + b_hh[layer * GG + col];
    }
    __syncthreads();

    int tb = tid & 15;       // b-tile (4 batches)
    int tc = tid >> 4;       // c-tile (4 cols)
    float c_reg[4] = {0.f, 0.f, 0.f, 0.f};

    u64 biasp[4];
#pragma unroll
    for (int j = 0; j < 4; j++) {
        float bv = bias_s[4 * tc + j];
        biasp[j] = pack2(bv, bv);
    }

    const ulonglong2* aU = (const ulonglong2*)a_s;   // [k][16]
    const ulonglong2* wU = (const ulonglong2*)w2_s;  // [k][16]

    volatile unsigned int* done = (volatile unsigned int*)g_done;

    for (int t = 0; t < TT; t++) {
        // ---- flow-control waits (thread 0 polls, block follows) ----
        if (tid == 0) {
            if (layer > 0) while (done[(layer - 1) * 32] < 16u * (t + 1)) { }
            if (t > 0)     while (done[layer * 32]       < 16u * t) { }
            if (layer < LL - 1 && t >= 2)
                while (done[(layer + 1) * 32] < 16u * (t - 1)) { }
            __threadfence();
        }
        __syncthreads();

        // ---- stage A = [inp ; h(t-1)] into smem ----
        // input h_{l-1}(t) lives in buffer (t & 1): written at layer l-1's step t.
        // own  h_l(t-1)   lives in buffer ((t+1) & 1): written at our step t-1.
        const float4* i4 = (layer == 0)
            ? (const float4*)&g_xe[t][0][0]
            : (const float4*)&g_hbuf[t & 1][layer - 1][0][0];
        const float4* h4 = (const float4*)&g_hbuf[(t + 1) & 1][layer][0][0];
        float4* a4 = (float4*)a_s;
        for (int i = tid; i < 2048; i += NTHR) a4[i] = i4[i];
        for (int i = tid; i < 2048; i += NTHR) a4[2048 + i] = h4[i];
        __syncthreads();

        // ---- GEMM via packed f32x2: acc[2 bpair][4 c] over K=256 ----
        u64 acc[2][4];
#pragma unroll
        for (int j = 0; j < 4; j++) { acc[0][j] = biasp[j]; acc[1][j] = biasp[j]; }

#pragma unroll 8
        for (int k = 0; k < 256; k++) {
            ulonglong2 av  = aU[k * 16 + tb];        // (b0b1, b2b3)
            ulonglong2 w01 = wU[k * 16 + 2 * tc];    // c0 dup, c1 dup
            ulonglong2 w23 = wU[k * 16 + 2 * tc + 1];
            FMA2(acc[0][0], av.x, w01.x); FMA2(acc[1][0], av.y, w01.x);
            FMA2(acc[0][1], av.x, w01.y); FMA2(acc[1][1], av.y, w01.y);
            FMA2(acc[0][2], av.x, w23.x); FMA2(acc[1][2], av.y, w23.x);
            FMA2(acc[0][3], av.x, w23.y); FMA2(acc[1][3], av.y, w23.y);
        }
        __syncthreads();     // done reading a_s

        // ---- gate exchange: g_sm[c][b] ----
#pragma unroll
        for (int j = 0; j < 4; j++) {
            u64* dst = (u64*)(g_sm + (4 * tc + j) * 64 + 4 * tb);
            dst[0] = acc[0][j];
            dst[1] = acc[1][j];
        }
        __syncthreads();

        // ---- fused elementwise ----
        int b = tid & 63;
#pragma unroll
        for (int ii = 0; ii < 4; ii++) {
            int j = (tid >> 6) + 2 * ii;
            float gi = g_sm[(0  + j) * 64 + b];
            float gf = g_sm[(8  + j) * 64 + b];
            float gg = g_sm[(16 + j) * 64 + b];
            float go = g_sm[(24 + j) * 64 + b];
            float iv = sigf(gi);
            float fv = sigf(gf);
            float gv = tanhf_(gg);
            float ov = sigf(go);
            float cp = (t == 0) ? 0.0f : c_reg[ii];
            float cn = fv * cp + iv * gv;
            float hv = ov * tanhf_(cn);
            c_reg[ii] = cn;
            g_hbuf[t & 1][layer][hc0 + j][b] = hv;
            if (layer == LL - 1) g_h7[t][hc0 + j][b] = hv;
            if (t == TT - 1 && out_size >= TOTALOUT) {
                long long base = OUTBASE + ((long long)layer * BB + b) * HH + hc0 + j;
                d_out[base] = hv;
                d_out[base + STATESZ] = cn;
            }
        }
        __threadfence();
        __syncthreads();
        if (tid == 0) atomicAdd((unsigned int*)&g_done[layer * 32], 1u);
    }
}

// ---------------- phase C: output projection ------------------------------
__global__ void proj_kernel(const float* __restrict__ w_out,
                            const float* __restrict__ b_out,
                            float* __restrict__ d_out) {
    int t = blockIdx.x;
    __shared__ float h_s[HH * BB];
    int tid = threadIdx.x;
    const float4* src = (const float4*)&g_h7[t][0][0];
    float4* dst4 = (float4*)h_s;
    for (int i = tid; i < 2048; i += 128) dst4[i] = src[i];
    __syncthreads();
    for (int idx = tid; idx < BB * OUTD; idx += 128) {
        int b = idx / OUTD, o = idx % OUTD;
        float acc = b_out[o];
#pragma unroll 8
        for (int k = 0; k < HH; k++)
            acc += h_s[k * 64 + b] * w_out[k * OUTD + o];
        d_out[((long long)b * TT + t) * OUTD + o] = acc;
    }
}

// ---------------- launch ---------------------------------------------------
extern "C" void kernel_launch(void* const* d_in, const int* in_sizes, int n_in,
                              void* d_out, int out_size) {
    const int*   x     = (const int*)d_in[0];
    const float* embed = (const float*)d_in[1];
    const float* w_ih  = (const float*)d_in[2];
    const float* b_ih  = (const float*)d_in[3];
    const float* w_hh  = (const float*)d_in[4];
    const float* b_hh  = (const float*)d_in[5];
    const float* w_out = (const float*)d_in[6];
    const float* b_out = (const float*)d_in[7];
    float* out = (float*)d_out;

    size_t smem_bytes = (16384 + 16384 + 32) * sizeof(float);   // ~128.1 KB
    cudaFuncSetAttribute(lstm_kernel, cudaFuncAttributeMaxDynamicSharedMemorySize,
                         (int)smem_bytes);

    init_kernel<<<64, 256>>>();
    embed_kernel<<<TT, 128>>>(x, embed);
    lstm_kernel<<<NCTA, NTHR, smem_bytes>>>(w_ih, b_ih, w_hh, b_hh, out,
                                            (long long)out_size);
    proj_kernel<<<TT, 128>>>(w_out, b_out, out);
}

// round 6
// speedup vs baseline: 1.0705x; 1.0571x over previous
#include <cuda_runtime.h>

#define BB 64
#define TT 512
#define HH 128
#define LL 8
#define OUTD 65
#define GG 512
#define CTAS_PER_LAYER 16
#define LSTM_CTAS (LL * CTAS_PER_LAYER)   // 128
#define PROJ_CTAS 16
#define NCTA (LSTM_CTAS + PROJ_CTAS)      // 144
#define NTHR 256

#define OUTBASE ((long long)BB * TT * OUTD)
#define STATESZ ((long long)LL * BB * HH)
#define TOTALOUT (OUTBASE + 2 * STATESZ)

typedef unsigned long long u64;
typedef unsigned int u32;

// ---------------- device scratch ------------------------------------------
__device__ float g_ring[4][LL][HH][BB];   // 4-deep h ring, k-major
__device__ float g_xe[TT][HH][BB];        // embedded input, k-major
__device__ float g_h7[TT][HH][BB];        // layer-7 h stream
__device__ u32 g_done[LL * 32];           // per-layer counters (64B apart)

// ---------------- helpers -------------------------------------------------
__device__ __forceinline__ float sigf(float x) { return 1.0f / (1.0f + __expf(-x)); }
__device__ __forceinline__ float tanhf_(float x) { return 2.0f / (1.0f + __expf(-2.0f * x)) - 1.0f; }
__device__ __forceinline__ u64 pack2(float x, float y) {
    u64 r; asm("mov.b64 %0, {%1,%2};" : "=l"(r) : "f"(x), "f"(y)); return r;
}
#define FMA2(d, a, b) \
    asm("fma.rn.f32x2 %0, %1, %2, %0;" : "+l"(d) : "l"(a), "l"(b))

__device__ __forceinline__ u32 ld_acq(const u32* p) {
    u32 v; asm volatile("ld.acquire.gpu.global.u32 %0, [%1];" : "=r"(v) : "l"(p)); return v;
}
__device__ __forceinline__ void red_rel(u32* p) {
    asm volatile("red.release.gpu.global.add.u32 [%0], %1;" :: "l"(p), "r"(1u) : "memory");
}
__device__ __forceinline__ u32 smem_u32(const void* p) {
    return (u32)__cvta_generic_to_shared(p);
}
#define CP16(s, g) asm volatile("cp.async.cg.shared.global [%0], [%1], 16;" :: "r"(s), "l"(g))
#define CP_COMMIT_WAIT() do { \
    asm volatile("cp.async.commit_group;"); \
    asm volatile("cp.async.wait_group 0;" ::: "memory"); } while (0)

// ---------------- init (replay-safe) --------------------------------------
__global__ void init_kernel() {
    long long n = 4LL * LL * HH * BB;
    float* p = &g_ring[0][0][0][0];
    long long i = (long long)blockIdx.x * blockDim.x + threadIdx.x;
    long long stride = (long long)gridDim.x * blockDim.x;
    for (; i < n; i += stride) p[i] = 0.0f;
    if (blockIdx.x == 0 && threadIdx.x < LL * 32) g_done[threadIdx.x] = 0u;
}

// ---------------- embedding gather, k-major -------------------------------
__global__ void embed_kernel(const int* __restrict__ x,
                             const float* __restrict__ embed) {
    int t = blockIdx.x;
    int tid = threadIdx.x;
    __shared__ int xv[BB];
    if (tid < BB) xv[tid] = x[tid * TT + t];
    __syncthreads();
    int b = tid >> 1, half = tid & 1;
    const float4* src = (const float4*)(embed + (long long)xv[b] * HH + half * 64);
#pragma unroll
    for (int i = 0; i < 16; i++) {
        float4 v = src[i];
        int k = half * 64 + i * 4;
        g_xe[t][k + 0][b] = v.x;
        g_xe[t][k + 1][b] = v.y;
        g_xe[t][k + 2][b] = v.z;
        g_xe[t][k + 3][b] = v.w;
    }
}

// ---------------- mega kernel: persistent LSTM + proj workers -------------
extern __shared__ float smem[];
// lstm CTA layout: w2_s u64[256*32] (64KB) | a_s float[16384] (64KB) | bias_s[32]
// proj CTA layout: w_s float[128*65] | bo_s float[80 pad] | h_s float[128*64] (16B-aligned)

__global__ void __launch_bounds__(NTHR, 1)
mega_kernel(const float* __restrict__ w_ih, const float* __restrict__ b_ih,
            const float* __restrict__ w_hh, const float* __restrict__ b_hh,
            const float* __restrict__ w_out, const float* __restrict__ b_out,
            float* __restrict__ d_out, long long out_size) {
    int tid = threadIdx.x;

    // =============== proj workers ===============
    if (blockIdx.x >= LSTM_CTAS) {
        int p = blockIdx.x - LSTM_CTAS;          // 0..15
        float* w_s = smem;                        // [128*65] = 8320 floats
        float* bo_s = smem + HH * OUTD;           // 80 floats (padded)
        float* h_s = smem + HH * OUTD + 80;       // 8400 floats -> 33600 B, 16B-aligned
        for (int i = tid; i < HH * OUTD; i += NTHR) w_s[i] = w_out[i];
        for (int i = tid; i < OUTD; i += NTHR) bo_s[i] = b_out[i];
        __syncthreads();
        u32 h_base = smem_u32(h_s);
        for (int t = p; t < TT; t += PROJ_CTAS) {
            if (tid == 0) {
                while (ld_acq(&g_done[(LL - 1) * 32]) < 16u * (t + 1)) { }
            }
            __syncthreads();
            const float4* src = (const float4*)&g_h7[t][0][0];
            for (int i = tid; i < 2048; i += NTHR)
                CP16(h_base + i * 16, (const void*)(src + i));
            CP_COMMIT_WAIT();
            __syncthreads();
            for (int idx = tid; idx < BB * OUTD; idx += NTHR) {
                int b = idx / OUTD, o = idx % OUTD;
                float acc = bo_s[o];
#pragma unroll 8
                for (int k = 0; k < HH; k++)
                    acc += h_s[k * 64 + b] * w_s[k * OUTD + o];
                d_out[((long long)b * TT + t) * OUTD + o] = acc;
            }
            __syncthreads();   // compute done before next h_s restage
        }
        return;
    }

    // =============== LSTM CTAs ===============
    u64*   w2_s   = (u64*)smem;                  // 8192 u64
    float* a_s    = smem + 16384;                // 16384 floats
    float* bias_s = smem + 16384 + 16384;        // 32 floats
    float* g_sm   = a_s;                         // gates alias [32][64]

    int layer = blockIdx.x / CTAS_PER_LAYER;
    int sub   = blockIdx.x % CTAS_PER_LAYER;
    int hc0   = sub * 8;

    // one-time weight slice -> smem (f32x2-duplicated)
    for (int idx = tid; idx < 128 * 32; idx += NTHR) {
        int k = idx >> 5, c = idx & 31;
        int col = (c >> 3) * HH + hc0 + (c & 7);
        float wi = w_ih[((long long)layer * HH + k) * GG + col];
        float wh = w_hh[((long long)layer * HH + k) * GG + col];
        w2_s[k * 32 + c]         = pack2(wi, wi);
        w2_s[(k + 128) * 32 + c] = pack2(wh, wh);
    }
    if (tid < 32) {
        int col = (tid >> 3) * HH + hc0 + (tid & 7);
        bias_s[tid] = b_ih[layer * GG + col] + b_hh[layer * GG + col];
    }
    __syncthreads();

    // GEMM thread mapping: team = cols [0..16)|[16..32); tb = 4-batch group; tc = 2-col group
    int team = tid >> 7;              // 0 or 1
    int q    = tid & 127;
    int tb   = q >> 3;                // 0..15
    int tc   = q & 7;                 // 0..7
    int c0   = team * 16 + 2 * tc;    // first of this thread's 2 cols

    u64 biasp[2];
    biasp[0] = pack2(bias_s[c0],     bias_s[c0]);
    biasp[1] = pack2(bias_s[c0 + 1], bias_s[c0 + 1]);

    // elementwise mapping: 2 cells per thread
    float c_reg[2] = {0.f, 0.f};

    const ulonglong2* aU = (const ulonglong2*)a_s;
    u32 a_base = smem_u32(a_s);

    for (int t = 0; t < TT; t++) {
        // ---- waits ----
        if (tid == 0) {
            if (layer > 0) while (ld_acq(&g_done[(layer - 1) * 32]) < 16u * (t + 1)) { }
            if (t > 0)     while (ld_acq(&g_done[layer * 32])       < 16u * t) { }
            if (layer < LL - 1 && t >= 4)
                while (ld_acq(&g_done[(layer + 1) * 32]) < 16u * (t - 3)) { }
        }
        __syncthreads();

        // ---- stage A = [inp(t) ; h(t-1)] via cp.async ----
        const float4* i4 = (layer == 0)
            ? (const float4*)&g_xe[t][0][0]
            : (const float4*)&g_ring[t & 3][layer - 1][0][0];
        const float4* h4 = (const float4*)&g_ring[(t - 1) & 3][layer][0][0];
        for (int i = tid; i < 2048; i += NTHR)
            CP16(a_base + i * 16, (const void*)(i4 + i));
        for (int i = tid; i < 2048; i += NTHR)
            CP16(a_base + 32768 + i * 16, (const void*)(h4 + i));
        CP_COMMIT_WAIT();
        __syncthreads();

        // ---- GEMM: 2 cols x 4 batches per thread over K=256 ----
        u64 acc[2][2];
        acc[0][0] = biasp[0]; acc[1][0] = biasp[0];
        acc[0][1] = biasp[1]; acc[1][1] = biasp[1];
#pragma unroll 8
        for (int k = 0; k < 256; k++) {
            ulonglong2 av = aU[k * 16 + tb];
            ulonglong2 wv = *(const ulonglong2*)&w2_s[k * 32 + c0];
            FMA2(acc[0][0], av.x, wv.x); FMA2(acc[1][0], av.y, wv.x);
            FMA2(acc[0][1], av.x, wv.y); FMA2(acc[1][1], av.y, wv.y);
        }
        __syncthreads();     // both teams done reading a_s

        // ---- gate exchange: g_sm[c][b] ----
#pragma unroll
        for (int cj = 0; cj < 2; cj++) {
            u64* dst = (u64*)(g_sm + (c0 + cj) * 64 + 4 * tb);
            dst[0] = acc[0][cj];
            dst[1] = acc[1][cj];
        }
        __syncthreads();

        // ---- fused elementwise: 2 cells/thread ----
#pragma unroll
        for (int ii = 0; ii < 2; ii++) {
            int cell = tid + ii * 256;           // 0..511
            int j = cell >> 6, b = cell & 63;
            float gi = g_sm[(0  + j) * 64 + b];
            float gf = g_sm[(8  + j) * 64 + b];
            float gg = g_sm[(16 + j) * 64 + b];
            float go = g_sm[(24 + j) * 64 + b];
            float iv = sigf(gi);
            float fv = sigf(gf);
            float gv = tanhf_(gg);
            float ov = sigf(go);
            float cp = (t == 0) ? 0.0f : c_reg[ii];
            float cn = fv * cp + iv * gv;
            float hv = ov * tanhf_(cn);
            c_reg[ii] = cn;
            g_ring[t & 3][layer][hc0 + j][b] = hv;
            if (layer == LL - 1) g_h7[t][hc0 + j][b] = hv;
            if (t == TT - 1 && out_size >= TOTALOUT) {
                long long base = OUTBASE + ((long long)layer * BB + b) * HH + hc0 + j;
                d_out[base] = hv;
                d_out[base + STATESZ] = cn;
            }
        }
        __syncthreads();     // stores done; also protects g_sm/a_s reuse
        if (tid == 0) red_rel(&g_done[layer * 32]);
    }
}

// ---------------- launch ---------------------------------------------------
extern "C" void kernel_launch(void* const* d_in, const int* in_sizes, int n_in,
                              void* d_out, int out_size) {
    const int*   x     = (const int*)d_in[0];
    const float* embed = (const float*)d_in[1];
    const float* w_ih  = (const float*)d_in[2];
    const float* b_ih  = (const float*)d_in[3];
    const float* w_hh  = (const float*)d_in[4];
    const float* b_hh  = (const float*)d_in[5];
    const float* w_out = (const float*)d_in[6];
    const float* b_out = (const float*)d_in[7];
    float* out = (float*)d_out;

    size_t smem_bytes = (16384 + 16384 + 64) * sizeof(float);   // ~128.25 KB
    cudaFuncSetAttribute(mega_kernel, cudaFuncAttributeMaxDynamicSharedMemorySize,
                         (int)smem_bytes);

    init_kernel<<<256, 256>>>();
    embed_kernel<<<TT, 128>>>(x, embed);
    mega_kernel<<<NCTA, NTHR, smem_bytes>>>(w_ih, b_ih, w_hh, b_hh,
                                            w_out, b_out, out, (long long)out_size);
}